// round 7
// baseline (speedup 1.0000x reference)
#include <cuda_runtime.h>

// SeparateLoss: mean over the N x N cosine-sim matrix masked by label
// inequality. Binary labels => (2/N^2) * dot(S0, S1),
// Sk = sum of L2-normalized feature rows with label k.
//
// feat [4, 64, 128, 128] f32, label [4, 1, 128, 128] i32.
// Nearest 128->64 picks even indices. N = 16384, C = 64.
//
// 128 blocks x 512 threads = ONE balanced wave on 148 SMs.
// Each block handles 2 output rows (thread halves), R6 pipeline per row:
// 8 x LDG.128 front-batched, sumsq in registers, float2 smem transpose.
// Last block (int ticket) reduces all partials in fixed order.

#define B 4
#define C 64
#define H 128
#define W 128
#define X 64
#define NROW 256                    // total output rows
#define NBLK 128                    // blocks (2 rows each)
#define NSLOT 128                   // (class, channel)
#define NTOT 16384.0f
#define TP 66                       // T pitch (floats)

__device__ __align__(16) float g_partial[NSLOT * NROW];  // [slot][row], fully rewritten
__device__ int g_ticket = 0;

__global__ void __launch_bounds__(512) separate_fused(
    const float* __restrict__ feat, const int* __restrict__ label,
    float* __restrict__ out)
{
    __shared__ float T[2][C * TP];     // per-row transposed values
    __shared__ float sq[2][8 * TP];    // per-row sumsq partials
    __shared__ float invn[2][X];
    __shared__ int   lab[2][X];
    __shared__ float G[2][2 * C * 5];  // [row][class][ch][q], pitch 5
    __shared__ float S[NSLOT];
    __shared__ int   is_last;

    const int bx   = blockIdx.x;       // 0..127
    const int tid  = threadIdx.x;      // 0..511
    const int half = tid >> 8;         // row within block
    const int t    = tid & 255;
    const int row  = 2 * bx + half;    // global output row 0..255
    const int b    = row >> 6;
    const int yi   = row & 63;
    const int g0   = t >> 5;           // channel-group base 0..7
    const int xj   = t & 31;           // float4 idx: positions 2xj, 2xj+1

    // ---- 8 x LDG.128: channels g0+8k, row y=2*yi ----
    const float4* fb = reinterpret_cast<const float4*>(
        feat + (((size_t)(b * C + g0) * H) + 2 * yi) * W) + xj;
    float4 v[8];
    #pragma unroll
    for (int k = 0; k < 8; k++)
        v[k] = fb[(size_t)(8 * k) * (H * W / 4)];

    if (t < X)
        lab[half][t] = label[b * (H * W) + 2 * yi * W + 2 * t];

    // ---- sumsq partials in registers (8 channels, 2 positions) ----
    {
        float p0 = 0.f, p1 = 0.f;
        #pragma unroll
        for (int k = 0; k < 8; k++) {
            p0 += v[k].x * v[k].x;     // pos 2xj
            p1 += v[k].z * v[k].z;     // pos 2xj+1
        }
        *reinterpret_cast<float2*>(&sq[half][g0 * TP + 2 * xj]) =
            make_float2(p0, p1);
    }
    // ---- transpose raw values: T[ch][pos] ----
    #pragma unroll
    for (int k = 0; k < 8; k++)
        *reinterpret_cast<float2*>(&T[half][(g0 + 8 * k) * TP + 2 * xj]) =
            make_float2(v[k].x, v[k].z);
    __syncthreads();

    // ---- inverse norms (fixed-order sum over 8 groups) ----
    if (t < X) {
        const float* q = sq[half];
        const float a = (q[0 * TP + t] + q[1 * TP + t]) +
                        (q[2 * TP + t] + q[3 * TP + t]);
        const float c = (q[4 * TP + t] + q[5 * TP + t]) +
                        (q[6 * TP + t] + q[7 * TP + t]);
        invn[half][t] = 1.0f / fmaxf(sqrtf(a + c), 1e-12f);
    }
    __syncthreads();

    // ---- class sums: thread (q, ch), 16 positions each ----
    {
        const int ch = t & 63;
        const int q  = t >> 6;         // 0..3
        float s0 = 0.f, s1 = 0.f;
        #pragma unroll
        for (int j = 0; j < 16; j++) {
            const int   p = q * 16 + j;
            const float c = T[half][ch * TP + p] * invn[half][p];
            if (lab[half][p] == 0) s0 += c; else s1 += c;
        }
        G[half][ch * 5 + q]         = s0;
        G[half][5 * C + ch * 5 + q] = s1;
    }
    __syncthreads();

    if (t < 128) {
        const int cls = t >> 6;
        const int ch  = t & 63;
        const float* g = G[half] + cls * (5 * C) + ch * 5;
        g_partial[(cls * C + ch) * NROW + row] = (g[0] + g[1]) + (g[2] + g[3]);
    }

    // ---- last-block ticket ----
    __threadfence();
    if (tid == 0) {
        const int tk = atomicAdd(&g_ticket, 1);
        is_last = (tk == NBLK - 1);
    }
    __syncthreads();
    if (!is_last) return;
    __threadfence();                   // acquire all partials

    // ---- deterministic final reduction: 4 threads/slot, 16 float4 each ----
    {
        const int slot = tid >> 2;     // 0..127
        const int part = tid & 3;
        const float4* p =
            reinterpret_cast<const float4*>(g_partial + slot * NROW) + part * 16;
        float acc = 0.f;
        #pragma unroll
        for (int i = 0; i < 16; i++) {
            const float4 u = p[i];
            acc += (u.x + u.y) + (u.z + u.w);
        }
        acc += __shfl_xor_sync(0xffffffffu, acc, 1);
        acc += __shfl_xor_sync(0xffffffffu, acc, 2);
        if (part == 0) S[slot] = acc;
    }
    __syncthreads();

    if (tid < 32) {
        float d = S[tid] * S[C + tid] + S[tid + 32] * S[C + tid + 32];
        #pragma unroll
        for (int o = 16; o > 0; o >>= 1)
            d += __shfl_down_sync(0xffffffffu, d, o);
        if (tid == 0) {
            out[0] = d * (2.0f / (NTOT * NTOT));
            g_ticket = 0;              // rearm for next replay
        }
    }
}

extern "C" void kernel_launch(void* const* d_in, const int* in_sizes, int n_in,
                              void* d_out, int out_size)
{
    const float* feat  = (const float*)d_in[0];
    const int*   label = (const int*)d_in[1];
    float*       out   = (float*)d_out;

    (void)in_sizes; (void)n_in; (void)out_size;

    separate_fused<<<NBLK, 512>>>(feat, label, out);
}